// round 7
// baseline (speedup 1.0000x reference)
#include <cuda_runtime.h>
#include <math.h>

#define BMAX 4096

// ---------------- scratch (device globals: allocation-guard safe) -------------
__device__ float g_K1[32 * 25];                       // dense 5x5 kernel, conv1
__device__ float g_K2[64 * 32 * 25];                  // dense 5x5 kernel, conv2
__device__ float g_H1[(size_t)BMAX * 32 * 14 * 14];   // after conv1+relu+pool
__device__ float g_H2[(size_t)BMAX * 64 * 7 * 7];     // after conv2+relu+pool
__device__ float g_F1[(size_t)BMAX * 128];            // after fc1+relu

// ---------------- DCLS kernel construction ------------------------------------
// pos = clip(p,-2,2)+2 in [0,4]; i=floor(pos); r=pos-i. The reference scatters
// into a 6x6 grid then trims row/col 5; any tap that would land there carries
// weight exactly 0 (r==0), so guarded skips are exact.
__global__ void scatter_k1(const float* __restrict__ w, const float* __restrict__ p) {
    int e = blockIdx.x * blockDim.x + threadIdx.x;
    if (e >= 32 * 1 * 16) return;
    int co = e / 16;
    float wv = w[e];
    float p1 = fminf(fmaxf(p[e], -2.f), 2.f) + 2.f;
    float p2 = fminf(fmaxf(p[512 + e], -2.f), 2.f) + 2.f;
    int i1 = (int)floorf(p1), i2 = (int)floorf(p2);
    float r1 = p1 - (float)i1, r2 = p2 - (float)i2;
    float* K = &g_K1[co * 25];
    atomicAdd(&K[i1 * 5 + i2], wv * (1.f - r1) * (1.f - r2));
    if (i1 + 1 < 5)               atomicAdd(&K[(i1 + 1) * 5 + i2],     wv * r1 * (1.f - r2));
    if (i2 + 1 < 5)               atomicAdd(&K[i1 * 5 + i2 + 1],       wv * (1.f - r1) * r2);
    if (i1 + 1 < 5 && i2 + 1 < 5) atomicAdd(&K[(i1 + 1) * 5 + i2 + 1], wv * r1 * r2);
}

__global__ void scatter_k2(const float* __restrict__ w, const float* __restrict__ p) {
    int e = blockIdx.x * blockDim.x + threadIdx.x;
    if (e >= 64 * 32 * 32) return;
    int co = e / (32 * 32);
    int ci = (e / 32) % 32;
    float wv = w[e];
    float p1 = fminf(fmaxf(p[e], -2.f), 2.f) + 2.f;
    float p2 = fminf(fmaxf(p[65536 + e], -2.f), 2.f) + 2.f;
    int i1 = (int)floorf(p1), i2 = (int)floorf(p2);
    float r1 = p1 - (float)i1, r2 = p2 - (float)i2;
    float* K = &g_K2[(co * 32 + ci) * 25];
    atomicAdd(&K[i1 * 5 + i2], wv * (1.f - r1) * (1.f - r2));
    if (i1 + 1 < 5)               atomicAdd(&K[(i1 + 1) * 5 + i2],     wv * r1 * (1.f - r2));
    if (i2 + 1 < 5)               atomicAdd(&K[i1 * 5 + i2 + 1],       wv * (1.f - r1) * r2);
    if (i1 + 1 < 5 && i2 + 1 < 5) atomicAdd(&K[(i1 + 1) * 5 + i2 + 1], wv * r1 * r2);
}

// ---------------- conv1 (1->32, 28x28, pad2) + relu + maxpool2 ----------------
// One block per image. Padded image in smem (32x32, pad 2 cancels conv pad).
// Each work item: one 2x2 pool cell x 4 output channels -> 4 input loads shared
// across 4 k-values per tap (ratio keeps FFMA the binding pipe).
__global__ __launch_bounds__(256) void conv1_k(const float* __restrict__ x,
                                               const float* __restrict__ b1) {
    __shared__ float xs[32 * 32];
    __shared__ float Ks[32 * 25];
    int img = blockIdx.x;
    int tid = threadIdx.x;
    for (int i = tid; i < 1024; i += 256) xs[i] = 0.f;
    for (int i = tid; i < 800; i += 256) Ks[i] = g_K1[i];
    __syncthreads();
    const float* xi = x + (size_t)img * 784;
    for (int i = tid; i < 784; i += 256) {
        int y = i / 28, xx = i % 28;
        xs[(y + 2) * 32 + xx + 2] = xi[i];
    }
    __syncthreads();

    for (int item = tid; item < 1568; item += 256) {   // 196 cells x 8 co-groups
        int cg = item / 196, cell = item % 196;
        int py = cell / 14, px = cell % 14, co0 = cg * 4;
        float acc[4][4];
        #pragma unroll
        for (int j = 0; j < 4; j++)
            #pragma unroll
            for (int q = 0; q < 4; q++) acc[j][q] = 0.f;

        #pragma unroll
        for (int dy = 0; dy < 5; dy++) {
            float a[6], b[6];
            const float* r0 = &xs[(2 * py + dy) * 32 + 2 * px];
            #pragma unroll
            for (int t = 0; t < 6; t++) { a[t] = r0[t]; b[t] = r0[32 + t]; }
            #pragma unroll
            for (int dx = 0; dx < 5; dx++) {
                #pragma unroll
                for (int j = 0; j < 4; j++) {
                    float k = Ks[(co0 + j) * 25 + dy * 5 + dx];
                    acc[j][0] = fmaf(k, a[dx],     acc[j][0]);
                    acc[j][1] = fmaf(k, a[dx + 1], acc[j][1]);
                    acc[j][2] = fmaf(k, b[dx],     acc[j][2]);
                    acc[j][3] = fmaf(k, b[dx + 1], acc[j][3]);
                }
            }
        }
        #pragma unroll
        for (int j = 0; j < 4; j++) {
            float m = fmaxf(fmaxf(acc[j][0], acc[j][1]), fmaxf(acc[j][2], acc[j][3]));
            m = fmaxf(m + b1[co0 + j], 0.f);
            g_H1[(((size_t)img * 32 + co0 + j) * 14 + py) * 14 + px] = m;
        }
    }
}

// ---------------- conv2 (32->64, 14x14, pad2) + relu + maxpool2 ---------------
// Grid (img, co-group of 16). Dyn smem: padded input 32x18x18 (41.5KB) +
// 16x32x25 kernel slice (51.2KB) = 92.7KB -> 2 CTAs/SM.
// Thread (tid<196): 2x2 pool cell x 4 co. Per (ci,dy): 12 row loads + 20 k
// loads feed 80 FMAs -> FFMA-pipe bound (0.4 LDS/FMA < 0.5 balance point).
__global__ __launch_bounds__(224) void conv2_k(const float* __restrict__ b2) {
    extern __shared__ float sm[];
    float* inS = sm;            // 32*18*18 = 10368 floats
    float* Ks  = sm + 10368;    // 16*32*25 = 12800 floats
    int img = blockIdx.x, cog = blockIdx.y;
    int tid = threadIdx.x;      // 224

    for (int i = tid; i < 10368; i += 224) inS[i] = 0.f;
    for (int i = tid; i < 12800; i += 224) Ks[i] = g_K2[cog * 12800 + i];
    __syncthreads();
    const float* h = &g_H1[(size_t)img * 32 * 196];
    for (int i = tid; i < 6272; i += 224) {
        int ci = i / 196, r = i % 196, y = r / 14, xx = r % 14;
        inS[ci * 324 + (y + 2) * 18 + xx + 2] = h[i];
    }
    __syncthreads();

    if (tid < 196) {
        int sub = tid / 49, cell = tid % 49;
        int py = cell / 7, px = cell % 7, co0 = sub * 4;
        float acc[4][4];
        #pragma unroll
        for (int j = 0; j < 4; j++)
            #pragma unroll
            for (int q = 0; q < 4; q++) acc[j][q] = 0.f;

        for (int ci = 0; ci < 32; ci++) {
            const float* base = &inS[ci * 324 + 2 * py * 18 + 2 * px];
            const float* kb = &Ks[co0 * 800 + ci * 25];
            #pragma unroll
            for (int dy = 0; dy < 5; dy++) {
                float a[6], b[6];
                const float* r0 = base + dy * 18;
                #pragma unroll
                for (int t = 0; t < 6; t++) { a[t] = r0[t]; b[t] = r0[18 + t]; }
                #pragma unroll
                for (int dx = 0; dx < 5; dx++) {
                    #pragma unroll
                    for (int j = 0; j < 4; j++) {
                        float k = kb[j * 800 + dy * 5 + dx];
                        acc[j][0] = fmaf(k, a[dx],     acc[j][0]);
                        acc[j][1] = fmaf(k, a[dx + 1], acc[j][1]);
                        acc[j][2] = fmaf(k, b[dx],     acc[j][2]);
                        acc[j][3] = fmaf(k, b[dx + 1], acc[j][3]);
                    }
                }
            }
        }
        #pragma unroll
        for (int j = 0; j < 4; j++) {
            int co = cog * 16 + co0 + j;
            float m = fmaxf(fmaxf(acc[j][0], acc[j][1]), fmaxf(acc[j][2], acc[j][3]));
            m = fmaxf(m + b2[co], 0.f);
            g_H2[((size_t)img * 64 + co) * 49 + cell] = m;
        }
    }
}

// ---------------- FC1: (B x 3136) @ (3136 x 128)^T + bias, relu ---------------
// Block: 32 rows x 128 cols, 256 threads, 4x4 thread tile, K-tile 32.
__global__ __launch_bounds__(256) void fc1_k(const float* __restrict__ W,
                                             const float* __restrict__ bias, int B) {
    __shared__ float As[32 * 33];    // [kk][m], pad 33 -> conflict-free
    __shared__ float Wt[32 * 129];   // [kk][c], pad 129 -> conflict-free
    int row0 = blockIdx.x * 32;
    int tid = threadIdx.x;
    int ty = tid >> 5, tx = tid & 31;
    float acc[4][4];
    #pragma unroll
    for (int i = 0; i < 4; i++)
        #pragma unroll
        for (int j = 0; j < 4; j++) acc[i][j] = 0.f;

    for (int kt = 0; kt < 3136; kt += 32) {
        #pragma unroll
        for (int q = 0; q < 4; q++) {           // A tile: 32x32, coalesced along k
            int l = tid + q * 256, kk = l & 31, m = l >> 5;
            As[kk * 33 + m] = g_H2[(size_t)(row0 + m) * 3136 + kt + kk];
        }
        #pragma unroll
        for (int q = 0; q < 16; q++) {          // W tile: 128x32, coalesced along k
            int l = tid + q * 256, kk = l & 31, c = l >> 5;
            Wt[kk * 129 + c] = W[(size_t)c * 3136 + kt + kk];
        }
        __syncthreads();
        #pragma unroll
        for (int kk = 0; kk < 32; kk++) {
            float a[4], w[4];
            #pragma unroll
            for (int i = 0; i < 4; i++) a[i] = As[kk * 33 + ty * 4 + i];
            #pragma unroll
            for (int j = 0; j < 4; j++) w[j] = Wt[kk * 129 + tx + 32 * j];
            #pragma unroll
            for (int i = 0; i < 4; i++)
                #pragma unroll
                for (int j = 0; j < 4; j++) acc[i][j] = fmaf(a[i], w[j], acc[i][j]);
        }
        __syncthreads();
    }
    #pragma unroll
    for (int i = 0; i < 4; i++) {
        int r = row0 + ty * 4 + i;
        if (r >= B) continue;
        #pragma unroll
        for (int j = 0; j < 4; j++) {
            int c = tx + 32 * j;
            g_F1[(size_t)r * 128 + c] = fmaxf(acc[i][j] + bias[c], 0.f);
        }
    }
}

// ---------------- FC2: (B x 128) @ (128 x 10)^T + bias ------------------------
__global__ __launch_bounds__(256) void fc2_k(const float* __restrict__ W,
                                             const float* __restrict__ bias,
                                             float* __restrict__ out, int B) {
    __shared__ float Ws[10 * 128];
    __shared__ float bs[10];
    int tid = threadIdx.x;
    for (int i = tid; i < 1280; i += 256) Ws[i] = W[i];
    if (tid < 10) bs[tid] = bias[tid];
    __syncthreads();
    int idx = blockIdx.x * 256 + tid;
    if (idx >= B * 10) return;
    int b = idx / 10, o = idx % 10;
    const float* f = &g_F1[(size_t)b * 128];
    float acc = bs[o];
    #pragma unroll
    for (int k = 0; k < 128; k++) acc = fmaf(f[k], Ws[o * 128 + k], acc);
    out[idx] = acc;
}

// ---------------- launch ------------------------------------------------------
extern "C" void kernel_launch(void* const* d_in, const int* in_sizes, int n_in,
                              void* d_out, int out_size) {
    const float* x     = (const float*)d_in[0];
    const float* w1    = (const float*)d_in[1];
    const float* p1    = (const float*)d_in[2];
    const float* b1    = (const float*)d_in[3];
    const float* w2    = (const float*)d_in[4];
    const float* p2    = (const float*)d_in[5];
    const float* b2    = (const float*)d_in[6];
    const float* fc1w  = (const float*)d_in[7];
    const float* fc1b  = (const float*)d_in[8];
    const float* fc2w  = (const float*)d_in[9];
    const float* fc2b  = (const float*)d_in[10];
    float* out = (float*)d_out;

    int B = in_sizes[0] / 784;
    if (B > BMAX) B = BMAX;

    void *k1p, *k2p;
    cudaGetSymbolAddress(&k1p, g_K1);
    cudaGetSymbolAddress(&k2p, g_K2);
    cudaMemsetAsync(k1p, 0, 32 * 25 * sizeof(float));
    cudaMemsetAsync(k2p, 0, 64 * 32 * 25 * sizeof(float));

    scatter_k1<<<2, 256>>>(w1, p1);
    scatter_k2<<<256, 256>>>(w2, p2);

    conv1_k<<<B, 256>>>(x, b1);

    cudaFuncSetAttribute(conv2_k, cudaFuncAttributeMaxDynamicSharedMemorySize, 92672);
    conv2_k<<<dim3(B, 4), 224, 92672>>>(b2);

    fc1_k<<<(B + 31) / 32, 256>>>(fc1w, fc1b, B);
    fc2_k<<<(B * 10 + 255) / 256, 256>>>(fc2w, fc2b, out, B);
}

// round 10
// speedup vs baseline: 1.6618x; 1.6618x over previous
#include <cuda_runtime.h>
#include <math.h>

#define BMAX 4096

// ---------------- scratch (device globals: allocation-guard safe) -------------
__device__ float g_K1[32 * 25];                       // dense 5x5 kernel, conv1
__device__ float g_K2[64 * 32 * 25];                  // dense 5x5 kernel, conv2
__device__ float g_H1[(size_t)BMAX * 196 * 32];       // conv1 out, CHANNELS-LAST [img][cell][ci]
__device__ float g_H2[(size_t)BMAX * 64 * 7 * 7];     // after conv2+relu+pool [img][co][cell]
__device__ float g_F1[(size_t)BMAX * 128];            // after fc1+relu

// ---------------- DCLS kernel construction ------------------------------------
__global__ void scatter_k1(const float* __restrict__ w, const float* __restrict__ p) {
    int e = blockIdx.x * blockDim.x + threadIdx.x;
    if (e >= 32 * 1 * 16) return;
    int co = e / 16;
    float wv = w[e];
    float p1 = fminf(fmaxf(p[e], -2.f), 2.f) + 2.f;
    float p2 = fminf(fmaxf(p[512 + e], -2.f), 2.f) + 2.f;
    int i1 = (int)floorf(p1), i2 = (int)floorf(p2);
    float r1 = p1 - (float)i1, r2 = p2 - (float)i2;
    float* K = &g_K1[co * 25];
    atomicAdd(&K[i1 * 5 + i2], wv * (1.f - r1) * (1.f - r2));
    if (i1 + 1 < 5)               atomicAdd(&K[(i1 + 1) * 5 + i2],     wv * r1 * (1.f - r2));
    if (i2 + 1 < 5)               atomicAdd(&K[i1 * 5 + i2 + 1],       wv * (1.f - r1) * r2);
    if (i1 + 1 < 5 && i2 + 1 < 5) atomicAdd(&K[(i1 + 1) * 5 + i2 + 1], wv * r1 * r2);
}

__global__ void scatter_k2(const float* __restrict__ w, const float* __restrict__ p) {
    int e = blockIdx.x * blockDim.x + threadIdx.x;
    if (e >= 64 * 32 * 32) return;
    int co = e / (32 * 32);
    int ci = (e / 32) % 32;
    float wv = w[e];
    float p1 = fminf(fmaxf(p[e], -2.f), 2.f) + 2.f;
    float p2 = fminf(fmaxf(p[65536 + e], -2.f), 2.f) + 2.f;
    int i1 = (int)floorf(p1), i2 = (int)floorf(p2);
    float r1 = p1 - (float)i1, r2 = p2 - (float)i2;
    float* K = &g_K2[(co * 32 + ci) * 25];
    atomicAdd(&K[i1 * 5 + i2], wv * (1.f - r1) * (1.f - r2));
    if (i1 + 1 < 5)               atomicAdd(&K[(i1 + 1) * 5 + i2],     wv * r1 * (1.f - r2));
    if (i2 + 1 < 5)               atomicAdd(&K[i1 * 5 + i2 + 1],       wv * (1.f - r1) * r2);
    if (i1 + 1 < 5 && i2 + 1 < 5) atomicAdd(&K[(i1 + 1) * 5 + i2 + 1], wv * r1 * r2);
}

// ---------------- conv1 (1->32, 28x28, pad2) + relu + maxpool2 ----------------
// Writes H1 CHANNELS-LAST: [img][cell(196)][ci(32)]. item = cell*8 + cg so that
// adjacent lanes hold adjacent co-groups of the same cell -> coalesced STG.
__global__ __launch_bounds__(256) void conv1_k(const float* __restrict__ x,
                                               const float* __restrict__ b1) {
    __shared__ float xs[32 * 32];
    __shared__ float Ks[32 * 25];
    int img = blockIdx.x;
    int tid = threadIdx.x;
    for (int i = tid; i < 1024; i += 256) xs[i] = 0.f;
    for (int i = tid; i < 800; i += 256) Ks[i] = g_K1[i];
    __syncthreads();
    const float* xi = x + (size_t)img * 784;
    for (int i = tid; i < 784; i += 256) {
        int y = i / 28, xx = i % 28;
        xs[(y + 2) * 32 + xx + 2] = xi[i];
    }
    __syncthreads();

    for (int item = tid; item < 1568; item += 256) {   // 196 cells x 8 co-groups
        int cg = item & 7, cell = item >> 3;
        int py = cell / 14, px = cell % 14, co0 = cg * 4;
        float acc[4][4];
        #pragma unroll
        for (int j = 0; j < 4; j++)
            #pragma unroll
            for (int q = 0; q < 4; q++) acc[j][q] = 0.f;

        #pragma unroll
        for (int dy = 0; dy < 5; dy++) {
            float a[6], b[6];
            const float* r0 = &xs[(2 * py + dy) * 32 + 2 * px];
            #pragma unroll
            for (int t = 0; t < 6; t++) { a[t] = r0[t]; b[t] = r0[32 + t]; }
            #pragma unroll
            for (int dx = 0; dx < 5; dx++) {
                #pragma unroll
                for (int j = 0; j < 4; j++) {
                    float k = Ks[(co0 + j) * 25 + dy * 5 + dx];
                    acc[j][0] = fmaf(k, a[dx],     acc[j][0]);
                    acc[j][1] = fmaf(k, a[dx + 1], acc[j][1]);
                    acc[j][2] = fmaf(k, b[dx],     acc[j][2]);
                    acc[j][3] = fmaf(k, b[dx + 1], acc[j][3]);
                }
            }
        }
        #pragma unroll
        for (int j = 0; j < 4; j++) {
            float m = fmaxf(fmaxf(acc[j][0], acc[j][1]), fmaxf(acc[j][2], acc[j][3]));
            m = fmaxf(m + b1[co0 + j], 0.f);
            g_H1[((size_t)img * 196 + cell) * 32 + co0 + j] = m;   // channels-last
        }
    }
}

// ---------------- conv2 via mma.sync tf32 implicit GEMM ----------------------
// Per CTA: (img, cog of 16 co). Tap-wise GEMM: for each of 25 taps,
//   C[m=196 spatial, n=16 co] += A_tap[m, ci=32] @ W_tap[ci, co]
// A channels-last in smem with ci-pitch 36 (conflict-free fragment gathers).
// 13 warps (416 thr): warp = one m16 tile, 2 n8 tiles. tf32 inputs (pre-rounded
// cvt.rna), fp32 accumulate. Epilogue: C -> smem (reuse inS) -> pool/relu/bias.
#define C2_SMEM_FLOATS (11664 + 12800)   // inS 18*18*36 + Ws 25*32*16
__global__ __launch_bounds__(416) void conv2_k(const float* __restrict__ b2) {
    extern __shared__ float sm[];
    float* inS = sm;            // [ (y)*18 + x ][ ci, pitch 36 ]  = 11664 floats
    float* Ws  = sm + 11664;    // [tap][ci][co16]                = 12800 floats
    int img = blockIdx.x, cog = blockIdx.y;
    int tid = threadIdx.x;

    for (int i = tid; i < 11664; i += 416) inS[i] = 0.f;
    for (int i = tid; i < 12800; i += 416) {
        int col = i & 15, ci = (i >> 4) & 31, tap = i >> 9;
        float v = g_K2[((cog * 16 + col) * 32 + ci) * 25 + tap];
        unsigned u; asm("cvt.rna.tf32.f32 %0, %1;" : "=r"(u) : "f"(v));
        Ws[i] = __uint_as_float(u);
    }
    __syncthreads();

    const float* h = g_H1 + (size_t)img * 6272;      // [cell][ci]
    for (int i = tid; i < 6272; i += 416) {
        int ci = i & 31, cell = i >> 5, y = cell / 14, xx = cell % 14;
        float v = h[i];
        unsigned u; asm("cvt.rna.tf32.f32 %0, %1;" : "=r"(u) : "f"(v));
        inS[((y + 2) * 18 + xx + 2) * 36 + ci] = __uint_as_float(u);
    }
    __syncthreads();

    int warp = tid >> 5, lane = tid & 31;
    int lk = lane & 3, ln = lane >> 2;
    // warp owns m-tile [warp*16, warp*16+16); fragment rows m0 (ln), m1 (ln+8)
    int m0 = warp * 16 + ln, m1 = m0 + 8;
    int mc0 = m0 < 196 ? m0 : 195, mc1 = m1 < 196 ? m1 : 195;   // clamp pad rows
    int y0 = mc0 / 14, x0 = mc0 % 14, y1 = mc1 / 14, x1 = mc1 % 14;

    float c[2][4] = {{0.f,0.f,0.f,0.f},{0.f,0.f,0.f,0.f}};

    for (int dy = 0; dy < 5; dy++) {
        #pragma unroll
        for (int dx = 0; dx < 5; dx++) {
            int tap = dy * 5 + dx;
            const float* wb = Ws + tap * 512 + lk * 16 + ln;    // + ks*128, +64 for k+4
            const float* p0 = inS + ((y0 + dy) * 18 + (x0 + dx)) * 36 + lk;
            const float* p1 = inS + ((y1 + dy) * 18 + (x1 + dx)) * 36 + lk;
            #pragma unroll
            for (int ks = 0; ks < 4; ks++) {
                unsigned a0 = __float_as_uint(p0[ks * 8]);
                unsigned a2 = __float_as_uint(p0[ks * 8 + 4]);
                unsigned a1 = __float_as_uint(p1[ks * 8]);
                unsigned a3 = __float_as_uint(p1[ks * 8 + 4]);
                #pragma unroll
                for (int nt = 0; nt < 2; nt++) {
                    unsigned b0 = __float_as_uint(wb[ks * 128 + nt * 8]);
                    unsigned b1 = __float_as_uint(wb[ks * 128 + 64 + nt * 8]);
                    asm volatile(
                        "mma.sync.aligned.m16n8k8.row.col.f32.tf32.tf32.f32 "
                        "{%0,%1,%2,%3}, {%4,%5,%6,%7}, {%8,%9}, {%0,%1,%2,%3};"
                        : "+f"(c[nt][0]), "+f"(c[nt][1]), "+f"(c[nt][2]), "+f"(c[nt][3])
                        : "r"(a0), "r"(a1), "r"(a2), "r"(a3), "r"(b0), "r"(b1));
                }
            }
        }
    }

    __syncthreads();                  // everyone done reading inS
    float* outS = sm;                 // reuse: [m][co16] pitch 17, 196*17 = 3332
    #pragma unroll
    for (int nt = 0; nt < 2; nt++) {
        int n = nt * 8 + 2 * lk;
        if (m0 < 196) { outS[m0 * 17 + n] = c[nt][0]; outS[m0 * 17 + n + 1] = c[nt][1]; }
        if (m1 < 196) { outS[m1 * 17 + n] = c[nt][2]; outS[m1 * 17 + n + 1] = c[nt][3]; }
    }
    __syncthreads();

    for (int i = tid; i < 784; i += 416) {            // 16 co x 49 cells
        int co = i / 49, cell = i % 49;
        int py = cell / 7, px = cell % 7;
        int mA = (2 * py) * 14 + 2 * px;
        float v = fmaxf(fmaxf(outS[mA * 17 + co],        outS[(mA + 1) * 17 + co]),
                        fmaxf(outS[(mA + 14) * 17 + co], outS[(mA + 15) * 17 + co]));
        v = fmaxf(v + b2[cog * 16 + co], 0.f);
        g_H2[((size_t)img * 64 + cog * 16 + co) * 49 + cell] = v;
    }
}

// ---------------- FC1: (B x 3136) @ (3136 x 128)^T + bias, relu ---------------
__global__ __launch_bounds__(256) void fc1_k(const float* __restrict__ W,
                                             const float* __restrict__ bias, int B) {
    __shared__ float As[32 * 33];
    __shared__ float Wt[32 * 129];
    int row0 = blockIdx.x * 32;
    int tid = threadIdx.x;
    int ty = tid >> 5, tx = tid & 31;
    float acc[4][4];
    #pragma unroll
    for (int i = 0; i < 4; i++)
        #pragma unroll
        for (int j = 0; j < 4; j++) acc[i][j] = 0.f;

    for (int kt = 0; kt < 3136; kt += 32) {
        #pragma unroll
        for (int q = 0; q < 4; q++) {
            int l = tid + q * 256, kk = l & 31, m = l >> 5;
            As[kk * 33 + m] = g_H2[(size_t)(row0 + m) * 3136 + kt + kk];
        }
        #pragma unroll
        for (int q = 0; q < 16; q++) {
            int l = tid + q * 256, kk = l & 31, cc = l >> 5;
            Wt[kk * 129 + cc] = W[(size_t)cc * 3136 + kt + kk];
        }
        __syncthreads();
        #pragma unroll
        for (int kk = 0; kk < 32; kk++) {
            float a[4], w[4];
            #pragma unroll
            for (int i = 0; i < 4; i++) a[i] = As[kk * 33 + ty * 4 + i];
            #pragma unroll
            for (int j = 0; j < 4; j++) w[j] = Wt[kk * 129 + tx + 32 * j];
            #pragma unroll
            for (int i = 0; i < 4; i++)
                #pragma unroll
                for (int j = 0; j < 4; j++) acc[i][j] = fmaf(a[i], w[j], acc[i][j]);
        }
        __syncthreads();
    }
    #pragma unroll
    for (int i = 0; i < 4; i++) {
        int r = row0 + ty * 4 + i;
        if (r >= B) continue;
        #pragma unroll
        for (int j = 0; j < 4; j++) {
            int cc = tx + 32 * j;
            g_F1[(size_t)r * 128 + cc] = fmaxf(acc[i][j] + bias[cc], 0.f);
        }
    }
}

// ---------------- FC2: (B x 128) @ (128 x 10)^T + bias ------------------------
__global__ __launch_bounds__(256) void fc2_k(const float* __restrict__ W,
                                             const float* __restrict__ bias,
                                             float* __restrict__ out, int B) {
    __shared__ float Wsm[10 * 128];
    __shared__ float bs[10];
    int tid = threadIdx.x;
    for (int i = tid; i < 1280; i += 256) Wsm[i] = W[i];
    if (tid < 10) bs[tid] = bias[tid];
    __syncthreads();
    int idx = blockIdx.x * 256 + tid;
    if (idx >= B * 10) return;
    int b = idx / 10, o = idx % 10;
    const float* f = &g_F1[(size_t)b * 128];
    float acc = bs[o];
    #pragma unroll
    for (int k = 0; k < 128; k++) acc = fmaf(f[k], Wsm[o * 128 + k], acc);
    out[idx] = acc;
}

// ---------------- launch ------------------------------------------------------
extern "C" void kernel_launch(void* const* d_in, const int* in_sizes, int n_in,
                              void* d_out, int out_size) {
    const float* x     = (const float*)d_in[0];
    const float* w1    = (const float*)d_in[1];
    const float* p1    = (const float*)d_in[2];
    const float* b1    = (const float*)d_in[3];
    const float* w2    = (const float*)d_in[4];
    const float* p2    = (const float*)d_in[5];
    const float* b2    = (const float*)d_in[6];
    const float* fc1w  = (const float*)d_in[7];
    const float* fc1b  = (const float*)d_in[8];
    const float* fc2w  = (const float*)d_in[9];
    const float* fc2b  = (const float*)d_in[10];
    float* out = (float*)d_out;

    int B = in_sizes[0] / 784;
    if (B > BMAX) B = BMAX;

    void *k1p, *k2p;
    cudaGetSymbolAddress(&k1p, g_K1);
    cudaGetSymbolAddress(&k2p, g_K2);
    cudaMemsetAsync(k1p, 0, 32 * 25 * sizeof(float));
    cudaMemsetAsync(k2p, 0, 64 * 32 * 25 * sizeof(float));

    scatter_k1<<<2, 256>>>(w1, p1);
    scatter_k2<<<256, 256>>>(w2, p2);

    conv1_k<<<B, 256>>>(x, b1);

    cudaFuncSetAttribute(conv2_k, cudaFuncAttributeMaxDynamicSharedMemorySize,
                         C2_SMEM_FLOATS * (int)sizeof(float));
    conv2_k<<<dim3(B, 4), 416, C2_SMEM_FLOATS * sizeof(float)>>>(b2);

    fc1_k<<<(B + 31) / 32, 256>>>(fc1w, fc1b, B);
    fc2_k<<<(B * 10 + 255) / 256, 256>>>(fc2w, fc2b, out, B);
}

// round 12
// speedup vs baseline: 4.1400x; 2.4913x over previous
#include <cuda_runtime.h>
#include <cuda_fp16.h>
#include <math.h>

#define BMAX 4096

// ---------------- scratch (device globals: allocation-guard safe) -------------
__device__ float g_K1[32 * 25];                        // dense 5x5 kernel, conv1
__device__ float g_K2[64 * 32 * 25];                   // dense 5x5 kernel, conv2
__device__ __align__(16) __half g_K2h[4 * 25 * 512];   // permuted fp16 [cog][tap][co16][t4][8]
__device__ __align__(16) __half g_H1h[(size_t)BMAX * 196 * 32]; // conv1 out, perm ch-last fp16
__device__ float g_H2[(size_t)BMAX * 64 * 7 * 7];      // after conv2+relu+pool [img][co][cell]
__device__ float g_F1[(size_t)BMAX * 128];             // after fc1+relu

// perm(ci): stored idx = t*8 + s*2 + b  where ci = s*8 + t*2 + b
// => each lane (t) finds its 8 fragment halves (s=0..3, b=0..1) contiguous (16B).

// ---------------- DCLS kernel construction ------------------------------------
__global__ void scatter_k1(const float* __restrict__ w, const float* __restrict__ p) {
    int e = blockIdx.x * blockDim.x + threadIdx.x;
    if (e >= 32 * 1 * 16) return;
    int co = e / 16;
    float wv = w[e];
    float p1 = fminf(fmaxf(p[e], -2.f), 2.f) + 2.f;
    float p2 = fminf(fmaxf(p[512 + e], -2.f), 2.f) + 2.f;
    int i1 = (int)floorf(p1), i2 = (int)floorf(p2);
    float r1 = p1 - (float)i1, r2 = p2 - (float)i2;
    float* K = &g_K1[co * 25];
    atomicAdd(&K[i1 * 5 + i2], wv * (1.f - r1) * (1.f - r2));
    if (i1 + 1 < 5)               atomicAdd(&K[(i1 + 1) * 5 + i2],     wv * r1 * (1.f - r2));
    if (i2 + 1 < 5)               atomicAdd(&K[i1 * 5 + i2 + 1],       wv * (1.f - r1) * r2);
    if (i1 + 1 < 5 && i2 + 1 < 5) atomicAdd(&K[(i1 + 1) * 5 + i2 + 1], wv * r1 * r2);
}

__global__ void scatter_k2(const float* __restrict__ w, const float* __restrict__ p) {
    int e = blockIdx.x * blockDim.x + threadIdx.x;
    if (e >= 64 * 32 * 32) return;
    int co = e / (32 * 32);
    int ci = (e / 32) % 32;
    float wv = w[e];
    float p1 = fminf(fmaxf(p[e], -2.f), 2.f) + 2.f;
    float p2 = fminf(fmaxf(p[65536 + e], -2.f), 2.f) + 2.f;
    int i1 = (int)floorf(p1), i2 = (int)floorf(p2);
    float r1 = p1 - (float)i1, r2 = p2 - (float)i2;
    float* K = &g_K2[(co * 32 + ci) * 25];
    atomicAdd(&K[i1 * 5 + i2], wv * (1.f - r1) * (1.f - r2));
    if (i1 + 1 < 5)               atomicAdd(&K[(i1 + 1) * 5 + i2],     wv * r1 * (1.f - r2));
    if (i2 + 1 < 5)               atomicAdd(&K[i1 * 5 + i2 + 1],       wv * (1.f - r1) * r2);
    if (i1 + 1 < 5 && i2 + 1 < 5) atomicAdd(&K[(i1 + 1) * 5 + i2 + 1], wv * r1 * r2);
}

// pack g_K2 (float, [co][ci][tap]) into permuted fp16 slab [cog][tap][co16][t4][j8]
__global__ void pack_k2() {
    int i = blockIdx.x * 256 + threadIdx.x;
    if (i >= 4 * 12800) return;
    int cog = i / 12800, r = i % 12800;
    int tap = r >> 9, rr = r & 511;
    int co = rr >> 5, t = (rr >> 3) & 3, j = rr & 7;
    int ci = (j >> 1) * 8 + t * 2 + (j & 1);
    float v = g_K2[((cog * 16 + co) * 32 + ci) * 25 + tap];
    g_K2h[i] = __float2half_rn(v);
}

// ---------------- conv1 (1->32, 28x28, pad2) + relu + maxpool2 ----------------
// Emits H1 as permuted channels-last fp16: [img][cell][perm(ci)], via half2 pairs.
__global__ __launch_bounds__(256) void conv1_k(const float* __restrict__ x,
                                               const float* __restrict__ b1) {
    __shared__ float xs[32 * 32];
    __shared__ float Ks[32 * 25];
    int img = blockIdx.x;
    int tid = threadIdx.x;
    for (int i = tid; i < 1024; i += 256) xs[i] = 0.f;
    for (int i = tid; i < 800; i += 256) Ks[i] = g_K1[i];
    __syncthreads();
    const float* xi = x + (size_t)img * 784;
    for (int i = tid; i < 784; i += 256) {
        int y = i / 28, xx = i % 28;
        xs[(y + 2) * 32 + xx + 2] = xi[i];
    }
    __syncthreads();

    for (int item = tid; item < 1568; item += 256) {   // 196 cells x 8 co-groups
        int cg = item & 7, cell = item >> 3;
        int py = cell / 14, px = cell % 14, co0 = cg * 4;
        float acc[4][4];
        #pragma unroll
        for (int j = 0; j < 4; j++)
            #pragma unroll
            for (int q = 0; q < 4; q++) acc[j][q] = 0.f;

        #pragma unroll
        for (int dy = 0; dy < 5; dy++) {
            float a[6], b[6];
            const float* r0 = &xs[(2 * py + dy) * 32 + 2 * px];
            #pragma unroll
            for (int tq = 0; tq < 6; tq++) { a[tq] = r0[tq]; b[tq] = r0[32 + tq]; }
            #pragma unroll
            for (int dx = 0; dx < 5; dx++) {
                #pragma unroll
                for (int j = 0; j < 4; j++) {
                    float k = Ks[(co0 + j) * 25 + dy * 5 + dx];
                    acc[j][0] = fmaf(k, a[dx],     acc[j][0]);
                    acc[j][1] = fmaf(k, a[dx + 1], acc[j][1]);
                    acc[j][2] = fmaf(k, b[dx],     acc[j][2]);
                    acc[j][3] = fmaf(k, b[dx + 1], acc[j][3]);
                }
            }
        }
        float m[4];
        #pragma unroll
        for (int j = 0; j < 4; j++) {
            float v = fmaxf(fmaxf(acc[j][0], acc[j][1]), fmaxf(acc[j][2], acc[j][3]));
            m[j] = fmaxf(v + b1[co0 + j], 0.f);
        }
        // permuted half2 stores: ci pair (co0,co0+1) -> half2 idx t0*4+s; (co0+2,co0+3) -> (t0+1)*4+s
        int t0 = (co0 >> 1) & 3, s = co0 >> 3;
        __half2* dst = (__half2*)&g_H1h[((size_t)img * 196 + cell) * 32];
        dst[t0 * 4 + s]       = __floats2half2_rn(m[0], m[1]);
        dst[(t0 + 1) * 4 + s] = __floats2half2_rn(m[2], m[3]);
    }
}

// ---------------- conv2 via mma.sync fp16 implicit GEMM ----------------------
// Per CTA (img, cog of 16 co). Tap-wise: C[196,16] += A_tap[196,32] @ W_tap[32,16].
// fp16 fragments, fp32 accumulate. All fragment traffic via conflict-free LDS.128
// thanks to the ci permutation. smem 46.3KB -> 4 CTAs/SM.
#define C2_SMEM_BYTES (20736 + 25600)   // inS 324*32 halves + Ws 25*512 halves
__global__ __launch_bounds__(416) void conv2_k(const float* __restrict__ b2) {
    extern __shared__ __align__(16) char smraw[];
    uint4* inSv = (uint4*)smraw;                 // [pos(324)][4 uint4]  (32 halves/pos)
    uint4* Wsv  = (uint4*)(smraw + 20736);       // [tap][co16][t4] uint4
    int img = blockIdx.x, cog = blockIdx.y;
    int tid = threadIdx.x;

    for (int i = tid; i < 1296; i += 416) inSv[i] = make_uint4(0u, 0u, 0u, 0u);
    const uint4* Wg = (const uint4*)(g_K2h + cog * 12800);
    for (int i = tid; i < 1600; i += 416) Wsv[i] = Wg[i];
    __syncthreads();
    const uint4* h = (const uint4*)(g_H1h + (size_t)img * 6272);
    for (int i = tid; i < 784; i += 416) {
        int cell = i >> 2, q = i & 3;
        int y = cell / 14, xx = cell % 14;
        inSv[((y + 2) * 18 + xx + 2) * 4 + q] = h[i];
    }
    __syncthreads();

    int warp = tid >> 5, lane = tid & 31;
    int t = lane & 3, gid = lane >> 2;
    int m0 = warp * 16 + gid, m1 = m0 + 8;
    int mc0 = m0 < 196 ? m0 : 195, mc1 = m1 < 196 ? m1 : 195;
    int y0 = mc0 / 14, x0 = mc0 % 14, y1 = mc1 / 14, x1 = mc1 % 14;
    int base0 = (y0 * 18 + x0) * 4 + t;
    int base1 = (y1 * 18 + x1) * 4 + t;

    float c[2][4] = {{0.f,0.f,0.f,0.f},{0.f,0.f,0.f,0.f}};

    #pragma unroll
    for (int dy = 0; dy < 5; dy++) {
        #pragma unroll
        for (int dx = 0; dx < 5; dx++) {
            int tap = dy * 5 + dx;
            uint4 A0 = inSv[base0 + (dy * 18 + dx) * 4];
            uint4 A1 = inSv[base1 + (dy * 18 + dx) * 4];
            uint4 B0 = Wsv[tap * 64 + gid * 4 + t];
            uint4 B1 = Wsv[tap * 64 + (8 + gid) * 4 + t];
            // ks=0 (ci 0..15)
            asm volatile("mma.sync.aligned.m16n8k16.row.col.f32.f16.f16.f32 "
                "{%0,%1,%2,%3}, {%4,%5,%6,%7}, {%8,%9}, {%0,%1,%2,%3};"
                : "+f"(c[0][0]), "+f"(c[0][1]), "+f"(c[0][2]), "+f"(c[0][3])
                : "r"(A0.x), "r"(A1.x), "r"(A0.y), "r"(A1.y), "r"(B0.x), "r"(B0.y));
            asm volatile("mma.sync.aligned.m16n8k16.row.col.f32.f16.f16.f32 "
                "{%0,%1,%2,%3}, {%4,%5,%6,%7}, {%8,%9}, {%0,%1,%2,%3};"
                : "+f"(c[1][0]), "+f"(c[1][1]), "+f"(c[1][2]), "+f"(c[1][3])
                : "r"(A0.x), "r"(A1.x), "r"(A0.y), "r"(A1.y), "r"(B1.x), "r"(B1.y));
            // ks=1 (ci 16..31)
            asm volatile("mma.sync.aligned.m16n8k16.row.col.f32.f16.f16.f32 "
                "{%0,%1,%2,%3}, {%4,%5,%6,%7}, {%8,%9}, {%0,%1,%2,%3};"
                : "+f"(c[0][0]), "+f"(c[0][1]), "+f"(c[0][2]), "+f"(c[0][3])
                : "r"(A0.z), "r"(A1.z), "r"(A0.w), "r"(A1.w), "r"(B0.z), "r"(B0.w));
            asm volatile("mma.sync.aligned.m16n8k16.row.col.f32.f16.f16.f32 "
                "{%0,%1,%2,%3}, {%4,%5,%6,%7}, {%8,%9}, {%0,%1,%2,%3};"
                : "+f"(c[1][0]), "+f"(c[1][1]), "+f"(c[1][2]), "+f"(c[1][3])
                : "r"(A0.z), "r"(A1.z), "r"(A0.w), "r"(A1.w), "r"(B1.z), "r"(B1.w));
        }
    }

    __syncthreads();                  // all warps done reading inS
    float* outS = (float*)smraw;      // reuse: [m(196)][co16] pitch 17 = 3332 floats
    #pragma unroll
    for (int nt = 0; nt < 2; nt++) {
        int n = nt * 8 + 2 * t;
        if (m0 < 196) { outS[m0 * 17 + n] = c[nt][0]; outS[m0 * 17 + n + 1] = c[nt][1]; }
        if (m1 < 196) { outS[m1 * 17 + n] = c[nt][2]; outS[m1 * 17 + n + 1] = c[nt][3]; }
    }
    __syncthreads();

    for (int i = tid; i < 784; i += 416) {            // 16 co x 49 cells
        int co = i / 49, cell = i % 49;
        int py = cell / 7, px = cell % 7;
        int mA = (2 * py) * 14 + 2 * px;
        float v = fmaxf(fmaxf(outS[mA * 17 + co],        outS[(mA + 1) * 17 + co]),
                        fmaxf(outS[(mA + 14) * 17 + co], outS[(mA + 15) * 17 + co]));
        v = fmaxf(v + b2[cog * 16 + co], 0.f);
        g_H2[((size_t)img * 64 + cog * 16 + co) * 49 + cell] = v;
    }
}

// ---------------- FC1: (B x 3136) @ (3136 x 128)^T + bias, relu ---------------
__global__ __launch_bounds__(256) void fc1_k(const float* __restrict__ W,
                                             const float* __restrict__ bias, int B) {
    __shared__ float As[32 * 33];
    __shared__ float Wt[32 * 129];
    int row0 = blockIdx.x * 32;
    int tid = threadIdx.x;
    int ty = tid >> 5, tx = tid & 31;
    float acc[4][4];
    #pragma unroll
    for (int i = 0; i < 4; i++)
        #pragma unroll
        for (int j = 0; j < 4; j++) acc[i][j] = 0.f;

    for (int kt = 0; kt < 3136; kt += 32) {
        #pragma unroll
        for (int q = 0; q < 4; q++) {
            int l = tid + q * 256, kk = l & 31, m = l >> 5;
            As[kk * 33 + m] = g_H2[(size_t)(row0 + m) * 3136 + kt + kk];
        }
        #pragma unroll
        for (int q = 0; q < 16; q++) {
            int l = tid + q * 256, kk = l & 31, cc = l >> 5;
            Wt[kk * 129 + cc] = W[(size_t)cc * 3136 + kt + kk];
        }
        __syncthreads();
        #pragma unroll
        for (int kk = 0; kk < 32; kk++) {
            float a[4], w[4];
            #pragma unroll
            for (int i = 0; i < 4; i++) a[i] = As[kk * 33 + ty * 4 + i];
            #pragma unroll
            for (int j = 0; j < 4; j++) w[j] = Wt[kk * 129 + tx + 32 * j];
            #pragma unroll
            for (int i = 0; i < 4; i++)
                #pragma unroll
                for (int j = 0; j < 4; j++) acc[i][j] = fmaf(a[i], w[j], acc[i][j]);
        }
        __syncthreads();
    }
    #pragma unroll
    for (int i = 0; i < 4; i++) {
        int r = row0 + ty * 4 + i;
        if (r >= B) continue;
        #pragma unroll
        for (int j = 0; j < 4; j++) {
            int cc = tx + 32 * j;
            g_F1[(size_t)r * 128 + cc] = fmaxf(acc[i][j] + bias[cc], 0.f);
        }
    }
}

// ---------------- FC2: (B x 128) @ (128 x 10)^T + bias ------------------------
__global__ __launch_bounds__(256) void fc2_k(const float* __restrict__ W,
                                             const float* __restrict__ bias,
                                             float* __restrict__ out, int B) {
    __shared__ float Wsm[10 * 128];
    __shared__ float bs[10];
    int tid = threadIdx.x;
    for (int i = tid; i < 1280; i += 256) Wsm[i] = W[i];
    if (tid < 10) bs[tid] = bias[tid];
    __syncthreads();
    int idx = blockIdx.x * 256 + tid;
    if (idx >= B * 10) return;
    int b = idx / 10, o = idx % 10;
    const float* f = &g_F1[(size_t)b * 128];
    float acc = bs[o];
    #pragma unroll
    for (int k = 0; k < 128; k++) acc = fmaf(f[k], Wsm[o * 128 + k], acc);
    out[idx] = acc;
}

// ---------------- launch ------------------------------------------------------
extern "C" void kernel_launch(void* const* d_in, const int* in_sizes, int n_in,
                              void* d_out, int out_size) {
    const float* x     = (const float*)d_in[0];
    const float* w1    = (const float*)d_in[1];
    const float* p1    = (const float*)d_in[2];
    const float* b1    = (const float*)d_in[3];
    const float* w2    = (const float*)d_in[4];
    const float* p2    = (const float*)d_in[5];
    const float* b2    = (const float*)d_in[6];
    const float* fc1w  = (const float*)d_in[7];
    const float* fc1b  = (const float*)d_in[8];
    const float* fc2w  = (const float*)d_in[9];
    const float* fc2b  = (const float*)d_in[10];
    float* out = (float*)d_out;

    int B = in_sizes[0] / 784;
    if (B > BMAX) B = BMAX;

    void *k1p, *k2p;
    cudaGetSymbolAddress(&k1p, g_K1);
    cudaGetSymbolAddress(&k2p, g_K2);
    cudaMemsetAsync(k1p, 0, 32 * 25 * sizeof(float));
    cudaMemsetAsync(k2p, 0, 64 * 32 * 25 * sizeof(float));

    scatter_k1<<<2, 256>>>(w1, p1);
    scatter_k2<<<256, 256>>>(w2, p2);
    pack_k2<<<200, 256>>>();

    conv1_k<<<B, 256>>>(x, b1);

    cudaFuncSetAttribute(conv2_k, cudaFuncAttributeMaxDynamicSharedMemorySize, C2_SMEM_BYTES);
    conv2_k<<<dim3(B, 4), 416, C2_SMEM_BYTES>>>(b2);

    fc1_k<<<(B + 31) / 32, 256>>>(fc1w, fc1b, B);
    fc2_k<<<(B * 10 + 255) / 256, 256>>>(fc2w, fc2b, out, B);
}

// round 16
// speedup vs baseline: 5.7454x; 1.3878x over previous
#include <cuda_runtime.h>
#include <cuda_fp16.h>
#include <math.h>

#define BMAX 4096

// ---------------- scratch (device globals: allocation-guard safe) -------------
__device__ float g_K1[32 * 25];                        // dense 5x5 kernel, conv1
__device__ float g_K2[64 * 32 * 25];                   // dense 5x5 kernel, conv2
__device__ __align__(16) __half g_K2h[4 * 25 * 512];   // permuted fp16 [cog][tap][co16][t4][8]
__device__ __align__(16) __half g_H1h[(size_t)BMAX * 196 * 32]; // conv1 out, perm ch-last fp16
__device__ __align__(16) __half g_H2h[(size_t)BMAX * 3136];     // conv2 out fp16 [img][k=co*49+cell]
__device__ __align__(16) __half g_W1h[98 * 128 * 32];  // fc1 W fp16, [chunk98][n128][perm32]
__device__ float g_F1[(size_t)BMAX * 128];             // after fc1+relu

// perm within a 32-k chunk: stored = t*8 + s*2 + b  where k_local = s*8 + t*2 + b
// => lane t's 8 fragment halves (both mma k-steps) are one contiguous uint4.

// ---------------- DCLS kernel construction ------------------------------------
__global__ void scatter_k1(const float* __restrict__ w, const float* __restrict__ p) {
    int e = blockIdx.x * blockDim.x + threadIdx.x;
    if (e >= 32 * 1 * 16) return;
    int co = e / 16;
    float wv = w[e];
    float p1 = fminf(fmaxf(p[e], -2.f), 2.f) + 2.f;
    float p2 = fminf(fmaxf(p[512 + e], -2.f), 2.f) + 2.f;
    int i1 = (int)floorf(p1), i2 = (int)floorf(p2);
    float r1 = p1 - (float)i1, r2 = p2 - (float)i2;
    float* K = &g_K1[co * 25];
    atomicAdd(&K[i1 * 5 + i2], wv * (1.f - r1) * (1.f - r2));
    if (i1 + 1 < 5)               atomicAdd(&K[(i1 + 1) * 5 + i2],     wv * r1 * (1.f - r2));
    if (i2 + 1 < 5)               atomicAdd(&K[i1 * 5 + i2 + 1],       wv * (1.f - r1) * r2);
    if (i1 + 1 < 5 && i2 + 1 < 5) atomicAdd(&K[(i1 + 1) * 5 + i2 + 1], wv * r1 * r2);
}

__global__ void scatter_k2(const float* __restrict__ w, const float* __restrict__ p) {
    int e = blockIdx.x * blockDim.x + threadIdx.x;
    if (e >= 64 * 32 * 32) return;
    int co = e / (32 * 32);
    int ci = (e / 32) % 32;
    float wv = w[e];
    float p1 = fminf(fmaxf(p[e], -2.f), 2.f) + 2.f;
    float p2 = fminf(fmaxf(p[65536 + e], -2.f), 2.f) + 2.f;
    int i1 = (int)floorf(p1), i2 = (int)floorf(p2);
    float r1 = p1 - (float)i1, r2 = p2 - (float)i2;
    float* K = &g_K2[(co * 32 + ci) * 25];
    atomicAdd(&K[i1 * 5 + i2], wv * (1.f - r1) * (1.f - r2));
    if (i1 + 1 < 5)               atomicAdd(&K[(i1 + 1) * 5 + i2],     wv * r1 * (1.f - r2));
    if (i2 + 1 < 5)               atomicAdd(&K[i1 * 5 + i2 + 1],       wv * (1.f - r1) * r2);
    if (i1 + 1 < 5 && i2 + 1 < 5) atomicAdd(&K[(i1 + 1) * 5 + i2 + 1], wv * r1 * r2);
}

// pack g_K2 (float, [co][ci][tap]) into permuted fp16 slab [cog][tap][co16][t4][j8]
__global__ void pack_k2() {
    int i = blockIdx.x * 256 + threadIdx.x;
    if (i >= 4 * 12800) return;
    int cog = i / 12800, r = i % 12800;
    int tap = r >> 9, rr = r & 511;
    int co = rr >> 5, t = (rr >> 3) & 3, j = rr & 7;
    int ci = (j >> 1) * 8 + t * 2 + (j & 1);
    float v = g_K2[((cog * 16 + co) * 32 + ci) * 25 + tap];
    g_K2h[i] = __float2half_rn(v);
}

// pack fc1 W (float [n=128][k=3136]) -> permuted fp16 [chunk][n][perm32]
__global__ void pack_w1(const float* __restrict__ W) {
    int i = blockIdx.x * 256 + threadIdx.x;
    if (i >= 98 * 128 * 32) return;
    int pos = i & 31, n = (i >> 5) & 127, c = i >> 12;
    int t = pos >> 3, s = (pos >> 1) & 3, b = pos & 1;
    int k = c * 32 + s * 8 + t * 2 + b;
    g_W1h[i] = __float2half_rn(W[(size_t)n * 3136 + k]);
}

// ---------------- conv1 (1->32, 28x28, pad2) + relu + maxpool2 ----------------
// Emits H1 as permuted channels-last fp16: [img][cell][perm(ci)], via half2 pairs.
__global__ __launch_bounds__(256, 2) void conv1_k(const float* __restrict__ x,
                                                  const float* __restrict__ b1) {
    __shared__ float xs[32 * 32];
    __shared__ float Ks[32 * 25];
    int img = blockIdx.x;
    int tid = threadIdx.x;
    for (int i = tid; i < 1024; i += 256) xs[i] = 0.f;
    for (int i = tid; i < 800; i += 256) Ks[i] = g_K1[i];
    __syncthreads();
    const float* xi = x + (size_t)img * 784;
    for (int i = tid; i < 784; i += 256) {
        int y = i / 28, xx = i % 28;
        xs[(y + 2) * 32 + xx + 2] = xi[i];
    }
    __syncthreads();

    #pragma unroll 1
    for (int item = tid; item < 1568; item += 256) {   // 196 cells x 8 co-groups
        int cg = item & 7, cell = item >> 3;
        int py = cell / 14, px = cell % 14, co0 = cg * 4;
        float acc[4][4];
        #pragma unroll
        for (int j = 0; j < 4; j++)
            #pragma unroll
            for (int q = 0; q < 4; q++) acc[j][q] = 0.f;

        #pragma unroll
        for (int dy = 0; dy < 5; dy++) {
            float a[6], b[6];
            const float* r0 = &xs[(2 * py + dy) * 32 + 2 * px];
            #pragma unroll
            for (int tq = 0; tq < 6; tq++) { a[tq] = r0[tq]; b[tq] = r0[32 + tq]; }
            #pragma unroll
            for (int dx = 0; dx < 5; dx++) {
                #pragma unroll
                for (int j = 0; j < 4; j++) {
                    float k = Ks[(co0 + j) * 25 + dy * 5 + dx];
                    acc[j][0] = fmaf(k, a[dx],     acc[j][0]);
                    acc[j][1] = fmaf(k, a[dx + 1], acc[j][1]);
                    acc[j][2] = fmaf(k, b[dx],     acc[j][2]);
                    acc[j][3] = fmaf(k, b[dx + 1], acc[j][3]);
                }
            }
        }
        float m[4];
        #pragma unroll
        for (int j = 0; j < 4; j++) {
            float v = fmaxf(fmaxf(acc[j][0], acc[j][1]), fmaxf(acc[j][2], acc[j][3]));
            m[j] = fmaxf(v + b1[co0 + j], 0.f);
        }
        int t0 = (co0 >> 1) & 3, s = co0 >> 3;
        __half2* dst = (__half2*)&g_H1h[((size_t)img * 196 + cell) * 32];
        dst[t0 * 4 + s]       = __floats2half2_rn(m[0], m[1]);
        dst[(t0 + 1) * 4 + s] = __floats2half2_rn(m[2], m[3]);
    }
}

// ---------------- conv2 via mma.sync fp16 implicit GEMM ----------------------
#define C2_SMEM_BYTES (20736 + 25600)   // inS 324*32 halves + Ws 25*512 halves
__global__ __launch_bounds__(416) void conv2_k(const float* __restrict__ b2) {
    extern __shared__ __align__(16) char smraw[];
    uint4* inSv = (uint4*)smraw;                 // [pos(324)][4 uint4]  (32 halves/pos)
    uint4* Wsv  = (uint4*)(smraw + 20736);       // [tap][co16][t4] uint4
    int img = blockIdx.x, cog = blockIdx.y;
    int tid = threadIdx.x;

    for (int i = tid; i < 1296; i += 416) inSv[i] = make_uint4(0u, 0u, 0u, 0u);
    const uint4* Wg = (const uint4*)(g_K2h + cog * 12800);
    for (int i = tid; i < 1600; i += 416) Wsv[i] = Wg[i];
    __syncthreads();
    const uint4* h = (const uint4*)(g_H1h + (size_t)img * 6272);
    for (int i = tid; i < 784; i += 416) {
        int cell = i >> 2, q = i & 3;
        int y = cell / 14, xx = cell % 14;
        inSv[((y + 2) * 18 + xx + 2) * 4 + q] = h[i];
    }
    __syncthreads();

    int warp = tid >> 5, lane = tid & 31;
    int t = lane & 3, gid = lane >> 2;
    int m0 = warp * 16 + gid, m1 = m0 + 8;
    int mc0 = m0 < 196 ? m0 : 195, mc1 = m1 < 196 ? m1 : 195;
    int y0 = mc0 / 14, x0 = mc0 % 14, y1 = mc1 / 14, x1 = mc1 % 14;
    int base0 = (y0 * 18 + x0) * 4 + t;
    int base1 = (y1 * 18 + x1) * 4 + t;

    float c[2][4] = {{0.f,0.f,0.f,0.f},{0.f,0.f,0.f,0.f}};

    #pragma unroll
    for (int dy = 0; dy < 5; dy++) {
        #pragma unroll
        for (int dx = 0; dx < 5; dx++) {
            int tap = dy * 5 + dx;
            uint4 A0 = inSv[base0 + (dy * 18 + dx) * 4];
            uint4 A1 = inSv[base1 + (dy * 18 + dx) * 4];
            uint4 B0 = Wsv[tap * 64 + gid * 4 + t];
            uint4 B1 = Wsv[tap * 64 + (8 + gid) * 4 + t];
            asm volatile("mma.sync.aligned.m16n8k16.row.col.f32.f16.f16.f32 "
                "{%0,%1,%2,%3}, {%4,%5,%6,%7}, {%8,%9}, {%0,%1,%2,%3};"
                : "+f"(c[0][0]), "+f"(c[0][1]), "+f"(c[0][2]), "+f"(c[0][3])
                : "r"(A0.x), "r"(A1.x), "r"(A0.y), "r"(A1.y), "r"(B0.x), "r"(B0.y));
            asm volatile("mma.sync.aligned.m16n8k16.row.col.f32.f16.f16.f32 "
                "{%0,%1,%2,%3}, {%4,%5,%6,%7}, {%8,%9}, {%0,%1,%2,%3};"
                : "+f"(c[1][0]), "+f"(c[1][1]), "+f"(c[1][2]), "+f"(c[1][3])
                : "r"(A0.x), "r"(A1.x), "r"(A0.y), "r"(A1.y), "r"(B1.x), "r"(B1.y));
            asm volatile("mma.sync.aligned.m16n8k16.row.col.f32.f16.f16.f32 "
                "{%0,%1,%2,%3}, {%4,%5,%6,%7}, {%8,%9}, {%0,%1,%2,%3};"
                : "+f"(c[0][0]), "+f"(c[0][1]), "+f"(c[0][2]), "+f"(c[0][3])
                : "r"(A0.z), "r"(A1.z), "r"(A0.w), "r"(A1.w), "r"(B0.z), "r"(B0.w));
            asm volatile("mma.sync.aligned.m16n8k16.row.col.f32.f16.f16.f32 "
                "{%0,%1,%2,%3}, {%4,%5,%6,%7}, {%8,%9}, {%0,%1,%2,%3};"
                : "+f"(c[1][0]), "+f"(c[1][1]), "+f"(c[1][2]), "+f"(c[1][3])
                : "r"(A0.z), "r"(A1.z), "r"(A0.w), "r"(A1.w), "r"(B1.z), "r"(B1.w));
        }
    }

    __syncthreads();
    float* outS = (float*)smraw;      // reuse: [m(196)][co16] pitch 17
    #pragma unroll
    for (int nt = 0; nt < 2; nt++) {
        int n = nt * 8 + 2 * t;
        if (m0 < 196) { outS[m0 * 17 + n] = c[nt][0]; outS[m0 * 17 + n + 1] = c[nt][1]; }
        if (m1 < 196) { outS[m1 * 17 + n] = c[nt][2]; outS[m1 * 17 + n + 1] = c[nt][3]; }
    }
    __syncthreads();

    for (int i = tid; i < 784; i += 416) {            // 16 co x 49 cells
        int co = i / 49, cell = i % 49;
        int py = cell / 7, px = cell % 7;
        int mA = (2 * py) * 14 + 2 * px;
        float v = fmaxf(fmaxf(outS[mA * 17 + co],        outS[(mA + 1) * 17 + co]),
                        fmaxf(outS[(mA + 14) * 17 + co], outS[(mA + 15) * 17 + co]));
        v = fmaxf(v + b2[cog * 16 + co], 0.f);
        g_H2h[(size_t)img * 3136 + (cog * 16 + co) * 49 + cell] = __float2half_rn(v);
    }
}

// ---------------- FC1 via mma.sync fp16: (B x 3136) @ W^T + bias, relu --------
// CTA: 32m x 64n, k-tile 64 (2 chunks of 32). 8 warps: warp = (mt = w&1)*16 rows,
// (ng = w>>1)*16 cols. A staged with the chunk-permuted layout + c^(m&1) slot flip
// (paired rows in an LDS phase hit disjoint 64B halves -> conflict-free LDS.128).
__global__ __launch_bounds__(256) void fc1_k(const float* __restrict__ bias, int B) {
    __shared__ __align__(16) uint4 As[32 * 8];     // slot = m*8 + (c^(m&1))*4 + t
    __shared__ __align__(16) uint4 Ws[2 * 64 * 4]; // slot = (c*64 + n)*4 + t
    int row0 = blockIdx.x * 32;
    int nb = blockIdx.y * 64;
    int tid = threadIdx.x;
    int warp = tid >> 5, lane = tid & 31;
    int mt = warp & 1, ng = warp >> 1;
    int gid = lane >> 2, t = lane & 3;

    // A staging role: thread = (am 0..31, ag 0..7); gmem uint4 #ag of the 64-k tile
    int am = tid >> 3, ag = tid & 7;
    int ach = ag >> 2, ag3 = ag & 3;
    const uint4* Arow = (const uint4*)(g_H2h + (size_t)(row0 + am) * 3136);
    unsigned* AsW = (unsigned*)&As[am * 8 + ((ach ^ (am & 1)) << 2)];
    const uint4* Wg = (const uint4*)g_W1h;          // [chunk98][n128][t4]

    float c[2][4] = {{0.f,0.f,0.f,0.f},{0.f,0.f,0.f,0.f}};
    int mr0 = mt * 16 + gid, mr1 = mr0 + 8;

    for (int kt = 0; kt < 49; kt++) {
        uint4 av = Arow[kt * 8 + ag];
        uint4 wv0 = Wg[(size_t)(2 * kt) * 512 + nb * 4 + tid];
        uint4 wv1 = Wg[(size_t)(2 * kt + 1) * 512 + nb * 4 + tid];
        __syncthreads();                    // previous iter's reads done
        // permuted A store: av.x -> t'=0 ... av.w -> t'=3, 4B offset ag3
        AsW[0 * 4 + ag3] = av.x;
        AsW[1 * 4 + ag3] = av.y;
        AsW[2 * 4 + ag3] = av.z;
        AsW[3 * 4 + ag3] = av.w;
        Ws[tid]       = wv0;
        Ws[256 + tid] = wv1;
        __syncthreads();

        #pragma unroll
        for (int cl = 0; cl < 2; cl++) {
            uint4 A0 = As[mr0 * 8 + ((cl ^ (mr0 & 1)) << 2) + t];
            uint4 A1 = As[mr1 * 8 + ((cl ^ (mr1 & 1)) << 2) + t];
            uint4 B0 = Ws[(cl * 64 + ng * 16 + gid) * 4 + t];
            uint4 B1 = Ws[(cl * 64 + ng * 16 + 8 + gid) * 4 + t];
            asm volatile("mma.sync.aligned.m16n8k16.row.col.f32.f16.f16.f32 "
                "{%0,%1,%2,%3}, {%4,%5,%6,%7}, {%8,%9}, {%0,%1,%2,%3};"
                : "+f"(c[0][0]), "+f"(c[0][1]), "+f"(c[0][2]), "+f"(c[0][3])
                : "r"(A0.x), "r"(A1.x), "r"(A0.y), "r"(A1.y), "r"(B0.x), "r"(B0.y));
            asm volatile("mma.sync.aligned.m16n8k16.row.col.f32.f16.f16.f32 "
                "{%0,%1,%2,%3}, {%4,%5,%6,%7}, {%8,%9}, {%0,%1,%2,%3};"
                : "+f"(c[1][0]), "+f"(c[1][1]), "+f"(c[1][2]), "+f"(c[1][3])
                : "r"(A0.x), "r"(A1.x), "r"(A0.y), "r"(A1.y), "r"(B1.x), "r"(B1.y));
            asm volatile("mma.sync.aligned.m16n8k16.row.col.f32.f16.f16.f32 "
                "{%0,%1,%2,%3}, {%4,%5,%6,%7}, {%8,%9}, {%0,%1,%2,%3};"
                : "+f"(c[0][0]), "+f"(c[0][1]), "+f"(c[0][2]), "+f"(c[0][3])
                : "r"(A0.z), "r"(A1.z), "r"(A0.w), "r"(A1.w), "r"(B0.z), "r"(B0.w));
            asm volatile("mma.sync.aligned.m16n8k16.row.col.f32.f16.f16.f32 "
                "{%0,%1,%2,%3}, {%4,%5,%6,%7}, {%8,%9}, {%0,%1,%2,%3};"
                : "+f"(c[1][0]), "+f"(c[1][1]), "+f"(c[1][2]), "+f"(c[1][3])
                : "r"(A0.z), "r"(A1.z), "r"(A0.w), "r"(A1.w), "r"(B1.z), "r"(B1.w));
        }
    }

    int r0 = row0 + mr0, r1 = row0 + mr1;
    #pragma unroll
    for (int nt = 0; nt < 2; nt++) {
        int ncol = nb + ng * 16 + nt * 8 + 2 * t;
        float bb0 = bias[ncol], bb1 = bias[ncol + 1];
        g_F1[(size_t)r0 * 128 + ncol]     = fmaxf(c[nt][0] + bb0, 0.f);
        g_F1[(size_t)r0 * 128 + ncol + 1] = fmaxf(c[nt][1] + bb1, 0.f);
        g_F1[(size_t)r1 * 128 + ncol]     = fmaxf(c[nt][2] + bb0, 0.f);
        g_F1[(size_t)r1 * 128 + ncol + 1] = fmaxf(c[nt][3] + bb1, 0.f);
    }
}

// ---------------- FC2: (B x 128) @ (128 x 10)^T + bias ------------------------
__global__ __launch_bounds__(256) void fc2_k(const float* __restrict__ W,
                                             const float* __restrict__ bias,
                                             float* __restrict__ out, int B) {
    __shared__ float Wsm[10 * 128];
    __shared__ float bs[10];
    int tid = threadIdx.x;
    for (int i = tid; i < 1280; i += 256) Wsm[i] = W[i];
    if (tid < 10) bs[tid] = bias[tid];
    __syncthreads();
    int idx = blockIdx.x * 256 + tid;
    if (idx >= B * 10) return;
    int b = idx / 10, o = idx % 10;
    const float* f = &g_F1[(size_t)b * 128];
    float acc = bs[o];
    #pragma unroll
    for (int k = 0; k < 128; k++) acc = fmaf(f[k], Wsm[o * 128 + k], acc);
    out[idx] = acc;
}

// ---------------- launch ------------------------------------------------------
extern "C" void kernel_launch(void* const* d_in, const int* in_sizes, int n_in,
                              void* d_out, int out_size) {
    const float* x     = (const float*)d_in[0];
    const float* w1    = (const float*)d_in[1];
    const float* p1    = (const float*)d_in[2];
    const float* b1    = (const float*)d_in[3];
    const float* w2    = (const float*)d_in[4];
    const float* p2    = (const float*)d_in[5];
    const float* b2    = (const float*)d_in[6];
    const float* fc1w  = (const float*)d_in[7];
    const float* fc1b  = (const float*)d_in[8];
    const float* fc2w  = (const float*)d_in[9];
    const float* fc2b  = (const float*)d_in[10];
    float* out = (float*)d_out;

    int B = in_sizes[0] / 784;
    if (B > BMAX) B = BMAX;

    void *k1p, *k2p;
    cudaGetSymbolAddress(&k1p, g_K1);
    cudaGetSymbolAddress(&k2p, g_K2);
    cudaMemsetAsync(k1p, 0, 32 * 25 * sizeof(float));
    cudaMemsetAsync(k2p, 0, 64 * 32 * 25 * sizeof(float));

    scatter_k1<<<2, 256>>>(w1, p1);
    scatter_k2<<<256, 256>>>(w2, p2);
    pack_k2<<<200, 256>>>();
    pack_w1<<<(98 * 128 * 32 + 255) / 256, 256>>>(fc1w);

    conv1_k<<<B, 256>>>(x, b1);

    cudaFuncSetAttribute(conv2_k, cudaFuncAttributeMaxDynamicSharedMemorySize, C2_SMEM_BYTES);
    conv2_k<<<dim3(B, 4), 416, C2_SMEM_BYTES>>>(b2);

    fc1_k<<<dim3(B / 32, 2), 256>>>(fc1b, B);
    fc2_k<<<(B * 10 + 255) / 256, 256>>>(fc2w, fc2b, out, B);
}